// round 1
// baseline (speedup 1.0000x reference)
#include <cuda_runtime.h>

#define D          128
#define DV         (D / 4)      // 32 float4 per row
#define NWARPS     8
#define NTHREADS   256
#define CACHE_ROWS 80           // 80 rows * 512B = 40KB smem row cache
#define MAXB       16384
#define TR         32           // GEMM row tile

// Scratch (allocation-free per harness rules)
__device__ int   g_seg_start[MAXB + 1];
__device__ float g_pooled[(size_t)MAXB * D];

// ---------------------------------------------------------------------------
// Kernel 0: segment boundaries via binary search (batch is sorted ascending)
// g_seg_start[v] = lower_bound(batch, v), for v in [0, B]
// ---------------------------------------------------------------------------
__global__ void seg_bounds_kernel(const int* __restrict__ batch, int N, int B)
{
    int v = blockIdx.x * blockDim.x + threadIdx.x;
    if (v > B) return;
    int lo = 0, hi = N;
    while (lo < hi) {
        int mid = (lo + hi) >> 1;
        if (batch[mid] < v) lo = mid + 1; else hi = mid;
    }
    g_seg_start[v] = lo;
}

// ---------------------------------------------------------------------------
// Kernel 1: per-segment attention pooling.
// One CTA per segment. Pass 1: column sums -> coarse (+ smem row cache).
// Pass 2: att_i = <x_i, coarse>; accumulate x_i * att_i -> pooled (to gmem).
// Static smem ~45KB also caps occupancy at ~5 CTAs/SM so pass-2 hits L2.
// ---------------------------------------------------------------------------
__global__ void __launch_bounds__(NTHREADS)
attention_pool_kernel(const float4* __restrict__ x)
{
    __shared__ float4 s_partial[NWARPS][DV];       // 4KB  cross-warp reduce
    __shared__ float4 s_coarse[DV];                // 512B
    __shared__ float4 s_cache[CACHE_ROWS * DV];    // 40KB row cache

    const int b     = blockIdx.x;
    const int start = g_seg_start[b];
    const int end   = g_seg_start[b + 1];
    const int cnt   = end - start;
    const float inv = 1.0f / (float)(cnt > 0 ? cnt : 1);
    const int w     = threadIdx.x >> 5;
    const int lane  = threadIdx.x & 31;

    // ---- Pass 1: column sums (warp w handles rows start+w, start+w+8, ...) ----
    float4 s = make_float4(0.f, 0.f, 0.f, 0.f);
    int r = start + w;
    for (; r + 3 * NWARPS < end; r += 4 * NWARPS) {
        float4 v0 = x[(size_t)(r             ) * DV + lane];
        float4 v1 = x[(size_t)(r +     NWARPS) * DV + lane];
        float4 v2 = x[(size_t)(r + 2 * NWARPS) * DV + lane];
        float4 v3 = x[(size_t)(r + 3 * NWARPS) * DV + lane];
        int c0 = r - start;
        if (c0              < CACHE_ROWS) s_cache[(c0             ) * DV + lane] = v0;
        if (c0 +     NWARPS < CACHE_ROWS) s_cache[(c0 +     NWARPS) * DV + lane] = v1;
        if (c0 + 2 * NWARPS < CACHE_ROWS) s_cache[(c0 + 2 * NWARPS) * DV + lane] = v2;
        if (c0 + 3 * NWARPS < CACHE_ROWS) s_cache[(c0 + 3 * NWARPS) * DV + lane] = v3;
        s.x += v0.x + v1.x + v2.x + v3.x;
        s.y += v0.y + v1.y + v2.y + v3.y;
        s.z += v0.z + v1.z + v2.z + v3.z;
        s.w += v0.w + v1.w + v2.w + v3.w;
    }
    for (; r < end; r += NWARPS) {
        float4 v = x[(size_t)r * DV + lane];
        int ci = r - start;
        if (ci < CACHE_ROWS) s_cache[ci * DV + lane] = v;
        s.x += v.x; s.y += v.y; s.z += v.z; s.w += v.w;
    }
    s_partial[w][lane] = s;
    __syncthreads();
    if (threadIdx.x < 32) {
        float4 c = s_partial[0][lane];
#pragma unroll
        for (int i = 1; i < NWARPS; i++) {
            float4 t = s_partial[i][lane];
            c.x += t.x; c.y += t.y; c.z += t.z; c.w += t.w;
        }
        c.x *= inv; c.y *= inv; c.z *= inv; c.w *= inv;
        s_coarse[lane] = c;
    }
    __syncthreads();
    const float4 cf = s_coarse[lane];

    // ---- Pass 2: att + scaled accumulation (cached rows from smem, rest L2) ----
    float4 acc = make_float4(0.f, 0.f, 0.f, 0.f);
    r = start + w;
    for (; r + NWARPS < end; r += 2 * NWARPS) {
        int c0 = r - start;
        int c1 = c0 + NWARPS;
        float4 v0 = (c0 < CACHE_ROWS) ? s_cache[c0 * DV + lane]
                                      : x[(size_t)r * DV + lane];
        float4 v1 = (c1 < CACHE_ROWS) ? s_cache[c1 * DV + lane]
                                      : x[(size_t)(r + NWARPS) * DV + lane];
        float d0 = v0.x * cf.x + v0.y * cf.y + v0.z * cf.z + v0.w * cf.w;
        float d1 = v1.x * cf.x + v1.y * cf.y + v1.z * cf.z + v1.w * cf.w;
#pragma unroll
        for (int o = 16; o > 0; o >>= 1) {
            d0 += __shfl_xor_sync(0xffffffffu, d0, o);
            d1 += __shfl_xor_sync(0xffffffffu, d1, o);
        }
        acc.x += v0.x * d0 + v1.x * d1;
        acc.y += v0.y * d0 + v1.y * d1;
        acc.z += v0.z * d0 + v1.z * d1;
        acc.w += v0.w * d0 + v1.w * d1;
    }
    if (r < end) {
        int ci = r - start;
        float4 v = (ci < CACHE_ROWS) ? s_cache[ci * DV + lane]
                                     : x[(size_t)r * DV + lane];
        float d = v.x * cf.x + v.y * cf.y + v.z * cf.z + v.w * cf.w;
#pragma unroll
        for (int o = 16; o > 0; o >>= 1)
            d += __shfl_xor_sync(0xffffffffu, d, o);
        acc.x += v.x * d; acc.y += v.y * d; acc.z += v.z * d; acc.w += v.w * d;
    }
    s_partial[w][lane] = acc;
    __syncthreads();
    if (threadIdx.x < 32) {
        float4 p = s_partial[0][lane];
#pragma unroll
        for (int i = 1; i < NWARPS; i++) {
            float4 t = s_partial[i][lane];
            p.x += t.x; p.y += t.y; p.z += t.z; p.w += t.w;
        }
        p.x *= inv; p.y *= inv; p.z *= inv; p.w *= inv;
        ((float4*)g_pooled)[(size_t)b * DV + lane] = p;
    }
}

// ---------------------------------------------------------------------------
// Kernel 2: out[B,128] = pooled[B,128] @ W^T + bias.
// One CTA per 32-row tile, 128 threads (thread j = output column).
// W read per-thread-row (L1-resident, ~64KB), pooled tile staged in smem.
// ---------------------------------------------------------------------------
__global__ void __launch_bounds__(128)
out_gemm_kernel(const float* __restrict__ W, const float* __restrict__ bias,
                float* __restrict__ out, int B)
{
    __shared__ float sp[TR][D];   // 16KB
    const int rb   = blockIdx.x * TR;
    int rows = B - rb; if (rows > TR) rows = TR;

    const float4* src = (const float4*)(g_pooled + (size_t)rb * D);
    float4* dst = (float4*)sp;
    for (int i = threadIdx.x; i < rows * DV; i += 128) dst[i] = src[i];
    __syncthreads();

    const int j = threadIdx.x;           // output column 0..127
    float acc[TR];
    const float bj = bias[j];
#pragma unroll
    for (int r2 = 0; r2 < TR; r2++) acc[r2] = bj;

    const float4* W4  = (const float4*)(W + (size_t)j * D);
    const float4* sp4 = (const float4*)sp;
    for (int k = 0; k < DV; k++) {
        float4 wv = W4[k];
#pragma unroll
        for (int r2 = 0; r2 < TR; r2++) {
            float4 pv = sp4[r2 * DV + k];
            acc[r2] += pv.x * wv.x + pv.y * wv.y + pv.z * wv.z + pv.w * wv.w;
        }
    }
    for (int r2 = 0; r2 < rows; r2++)
        out[(size_t)(rb + r2) * D + j] = acc[r2];
}

// ---------------------------------------------------------------------------
extern "C" void kernel_launch(void* const* d_in, const int* in_sizes, int n_in,
                              void* d_out, int out_size)
{
    const float* x    = (const float*)d_in[0];
    const int*   batch= (const int*)  d_in[1];
    const float* W    = (const float*)d_in[2];
    const float* bias = (const float*)d_in[3];
    (void)n_in;

    const int N = in_sizes[1];          // number of rows
    const int B = out_size / D;         // number of segments

    int bblocks = (B + 1 + 255) / 256;
    seg_bounds_kernel<<<bblocks, 256>>>(batch, N, B);
    attention_pool_kernel<<<B, NTHREADS>>>((const float4*)x);
    out_gemm_kernel<<<(B + TR - 1) / TR, 128>>>(W, bias, (float*)d_out, B);
}